// round 8
// baseline (speedup 1.0000x reference)
#include <cuda_runtime.h>
#include <stdint.h>

#define NALGOS 64
#define NTASKS 1024
#define LXN    512
#define FULLMASK 0xffffffffu

// Scratch (no allocations allowed).
// g_G[s*512 + t] = TM[lx[s]][lx[t]]
__device__ float g_G[LXN * LXN];
__device__ float g_u[NALGOS * LXN];
__device__ int   g_flag[NALGOS * 128];    // 4 padded copies (32 ints apart) per algo

// 2*sigmoid(z) - 1 == tanh(z/2): single MUFU.TANH, abs err ~2^-11.
__device__ __forceinline__ float tanh_fast(float x) {
    float y;
    asm("tanh.approx.f32 %0, %1;" : "=f"(y) : "f"(x));
    return y;
}
__device__ __forceinline__ void st_release_gpu(int* p, int v) {
    asm volatile("st.release.gpu.global.u32 [%0], %1;" :: "l"(p), "r"(v) : "memory");
}
__device__ __forceinline__ int ld_acquire_gpu(const int* p) {
    int v;
    asm volatile("ld.acquire.gpu.global.u32 %0, [%1];" : "=r"(v) : "l"(p) : "memory");
    return v;
}
__device__ __forceinline__ float ldcg_f32(const float* p) {
    float v;
    asm volatile("ld.global.cg.f32 %0, [%1];" : "=f"(v) : "l"(p) : "memory");
    return v;
}
__device__ __forceinline__ void stcg_f32(float* p, float v) {
    asm volatile("st.global.cg.f32 [%0], %1;" :: "l"(p), "f"(v) : "memory");
}
__device__ __forceinline__ void stcs_f32(float* p, float v) {
    asm volatile("st.global.cs.f32 [%0], %1;" :: "l"(p), "f"(v) : "memory");
}

// ---------------------------------------------------------------------------
// Kernel 0: G[s][t] = TM[lx[s]][lx[t]]; also reset per-algo progress flags.
// ---------------------------------------------------------------------------
__global__ void build_G(const int* __restrict__ lx, const float* __restrict__ TM) {
    int s = blockIdx.x;
    int t = threadIdx.x;
    if (s == 0 && t < NALGOS * 4) g_flag[(t >> 2) * 128 + (t & 3) * 32] = 0;
    int row = __ldg(lx + s);
    int col = __ldg(lx + t);
    g_G[s * LXN + t] = __ldg(TM + row * NTASKS + col);
}

// ---------------------------------------------------------------------------
// Fused kernel: 320 co-resident blocks.
//   blocks 0..63   : phase1 blocked-scan chain. Chain critical path refactored
//                    to th->shfl->fma (50 cyc/step): g*eff and g*boost are
//                    precomputed off-path so the post-shfl work is one FMA.
//   blocks 64..319 : phase2, now WARP-AUTONOMOUS: no block barriers in the
//                    chunk loop. Each warp prefetches TM into registers,
//                    acquire-polls its own flag line, loads u into a register
//                    lane and shfl-broadcasts. Sigmoids go to smem 4-wide
//                    (STS.128), then 32 coalesced STG.32 rows per chunk.
// ---------------------------------------------------------------------------
__global__ void __launch_bounds__(256, 4) fused(
    const int* __restrict__ lx, const float* __restrict__ diff,
    const float* __restrict__ eff_, const float* __restrict__ mem_,
    const float* __restrict__ boost_, const float* __restrict__ TM,
    float* __restrict__ out) {

    __shared__ float u_sh[LXN];          // producer only
    __shared__ float big[8 * 32 * 36];   // p1: c2_sh+Bnext | p2: per-warp tbuf (pad 36)
    __shared__ int   off_sh[LXN];

    int bid = blockIdx.x;
    int tid = threadIdx.x;
    int w = tid >> 5, l = tid & 31;

    if (bid < NALGOS) {
        // ================= PHASE 1 =================
        int a = bid;
        float* c2_sh = big;
        float* Bnext = big + LXN;

        float mem = __ldg(mem_ + a), eff = __ldg(eff_ + a), boost = __ldg(boost_ + a);
        float m2 = mem * mem, m4 = m2 * m2, m8 = m4 * m4, m16 = m8 * m8;
        float M32 = m16 * m16;

        for (int t = tid; t < LXN; t += 256)
            c2_sh[t] = 0.5f / __ldg(diff + __ldg(lx + t));
        __syncthreads();

        if (w == 0) {
            // ---- chain warp: branch-free, 50-cyc/step critical path ----
            float racc = 0.0f, racc2 = 0.0f;
            float c2l = c2_sh[l];
            float my_u = 0.0f;

#pragma unroll 1
            for (int c = 0; c < 16; ++c) {
                int t0 = c * 32;
                const float* gArow = g_G + t0 + l;
                const float* gBrow = g_G + t0 + 32 + l;
                bool hasB = (c < 15);

                float gAe[8], gAb[8], gBe[8], gBb[8];
#pragma unroll
                for (int q = 0; q < 8; ++q) {
                    float ga = __ldg(gArow + (t0 + q) * LXN);
                    float gb = hasB ? __ldg(gBrow + (t0 + q) * LXN) : 0.0f;
                    gAe[q] = ga * eff;  gAb[q] = ga * boost;
                    gBe[q] = gb * eff;  gBb[q] = gb * boost;
                }
#pragma unroll
                for (int k = 0; k < 32; ++k) {
                    int q = k & 7;
                    float th = tanh_fast(racc * c2l);        // all lanes
                    float thb = __shfl_sync(FULLMASK, th, k);
                    // owner lane keeps its own u for publishing (no 2nd shfl)
                    my_u = (l == k) ? fmaf(th, boost, eff) : my_u;
                    racc  = fmaf(thb, gAb[q], fmaf(racc,  mem, gAe[q]));
                    racc2 = fmaf(thb, gBb[q], fmaf(racc2, mem, gBe[q]));
                    if (k + 8 < 32) {
                        float ga = __ldg(gArow + (t0 + k + 8) * LXN);
                        float gb = hasB ? __ldg(gBrow + (t0 + k + 8) * LXN) : 0.0f;
                        gAe[q] = ga * eff;  gAb[q] = ga * boost;
                        gBe[q] = gb * eff;  gBb[q] = gb * boost;
                    }
                }
                u_sh[t0 + l] = my_u;
                __syncthreads();
                if (c < 15) {
                    racc  = fmaf(Bnext[((c + 1) & 1) * 32 + l], M32, racc2);
                    racc2 = 0.0f;
                    c2l   = c2_sh[t0 + 32 + l];
                }
            }
        } else {
            // ---- bulk warps 1..7 ----
            int base0 = (w - 1) * 32 + l;
            bool has3 = (base0 + 448 < LXN);
            float R0 = 0.0f, R1 = 0.0f, R2v = 0.0f;

#pragma unroll 1
            for (int c = 0; c < 16; ++c) {
                if (c >= 1) {
                    int s0 = (c - 1) * 32;
                    const float* g0 = g_G + base0;
#pragma unroll 8
                    for (int k = 0; k < 32; ++k) {
                        float u = u_sh[s0 + k];
                        const float* gr = g0 + (s0 + k) * LXN;
                        R0 = fmaf(R0, mem, __ldg(gr) * u);
                        R1 = fmaf(R1, mem, __ldg(gr + 224) * u);
                        if (has3) R2v = fmaf(R2v, mem, __ldg(gr + 448) * u);
                    }
                }
                int b = c + 1;
                if (b <= 15 && (w - 1) == (b % 7)) {
                    int i = b / 7;
                    float Rv = (i == 0) ? R0 : (i == 1) ? R1 : R2v;
                    Bnext[(b & 1) * 32 + l] = Rv;
                }
                __syncthreads();
                if (w == 1) {
                    stcg_f32(g_u + a * LXN + c * 32 + l, u_sh[c * 32 + l]);
                    __threadfence();
                    __syncwarp();
                    if (l < 4) st_release_gpu(g_flag + a * 128 + l * 32, c + 1);
                }
            }
        }
    } else {
        // ================= PHASE 2 (warp-autonomous) =================
        int b  = bid - NALGOS;
        int a  = b >> 2;
        int jb = b & 3;
        int j  = jb * 256 + tid;
        float* tbuf = big + w * (32 * 36);       // [32 rows][36 floats], 16B-aligned

        for (int i = tid; i < LXN; i += 256)
            off_sh[i] = __ldg(lx + i) << 10;

        float mem = __ldg(mem_ + a);
        float c2  = 0.5f / __ldg(diff + j);
        float r   = 0.0f;

        unsigned obase = (unsigned)(a * NTASKS + j) * 513u;
        stcs_f32(out + obase, 0.0f);
        unsigned tbase = (unsigned)(a * NTASKS + jb * 256 + w * 32) * 513u
                         + 1u + (unsigned)l;
        const int* fp = g_flag + a * 128 + jb * 32;
        const float* TMj = TM + j;
        const float* up  = g_u + a * LXN + l;
        __syncthreads();                          // off_sh ready (only barrier)

#pragma unroll 1
        for (int c = 0; c < 16; ++c) {
            // 1) prefetch chunk's 32 TM values (independent of flag)
            float v[32];
#pragma unroll
            for (int k = 0; k < 32; ++k)
                v[k] = __ldg(TMj + off_sh[c * 32 + k]);
            // 2) per-warp acquire (all lanes poll: 1 broadcast wavefront)
            while (ld_acquire_gpu(fp) <= c) { }
            float u_c = ldcg_f32(up + c * 32);    // lane l holds u[c*32+l]
            // 3) compute; pack 4 sigmoids -> STS.128
#pragma unroll
            for (int g = 0; g < 8; ++g) {
                float4 s4;
                float uu;
                uu = __shfl_sync(FULLMASK, u_c, 4 * g + 0);
                r = fmaf(r, mem, v[4 * g + 0] * uu);  s4.x = tanh_fast(r * c2);
                uu = __shfl_sync(FULLMASK, u_c, 4 * g + 1);
                r = fmaf(r, mem, v[4 * g + 1] * uu);  s4.y = tanh_fast(r * c2);
                uu = __shfl_sync(FULLMASK, u_c, 4 * g + 2);
                r = fmaf(r, mem, v[4 * g + 2] * uu);  s4.z = tanh_fast(r * c2);
                uu = __shfl_sync(FULLMASK, u_c, 4 * g + 3);
                r = fmaf(r, mem, v[4 * g + 3] * uu);  s4.w = tanh_fast(r * c2);
                *(float4*)(tbuf + l * 36 + g * 4) = s4;
            }
            __syncwarp();
            // 4) coalesced streaming stores (STG.32: 513-stride +1 offset
            //    is not 16B-alignable, so .128 is impossible here)
            unsigned ob = tbase + (unsigned)(c * 32);
#pragma unroll 8
            for (int row = 0; row < 32; ++row)
                stcs_f32(out + ob + (unsigned)row * 513u, tbuf[row * 36 + l]);
            __syncwarp();
        }
    }
}

// ---------------------------------------------------------------------------
extern "C" void kernel_launch(void* const* d_in, const int* in_sizes, int n_in,
                              void* d_out, int out_size) {
    const int*   lx    = (const int*)  d_in[0];
    const float* TM    = (const float*)d_in[1];
    const float* diff  = (const float*)d_in[2];
    const float* eff   = (const float*)d_in[3];
    const float* mem   = (const float*)d_in[4];
    const float* boost = (const float*)d_in[5];
    float* out = (float*)d_out;

    build_G<<<LXN, LXN>>>(lx, TM);
    fused<<<NALGOS + NALGOS * 4, 256>>>(lx, diff, eff, mem, boost, TM, out);
}

// round 9
// speedup vs baseline: 1.0211x; 1.0211x over previous
#include <cuda_runtime.h>
#include <stdint.h>

#define NALGOS 64
#define NTASKS 1024
#define LXN    512
#define FULLMASK 0xffffffffu

// Scratch (no allocations allowed).
// g_G[s*512 + t] = TM[lx[s]][lx[t]]
__device__ float g_G[LXN * LXN];
__device__ float g_u[NALGOS * LXN];

// 2*sigmoid(z) - 1 == tanh(z/2): single MUFU.TANH, abs err ~2^-11.
__device__ __forceinline__ float tanh_fast(float x) {
    float y;
    asm("tanh.approx.f32 %0, %1;" : "=f"(y) : "f"(x));
    return y;
}
__device__ __forceinline__ void stcs_f32(float* p, float v) {
    asm volatile("st.global.cs.f32 [%0], %1;" :: "l"(p), "f"(v) : "memory");
}

// ---------------------------------------------------------------------------
// Kernel 0: G[s][t] = TM[lx[s]][lx[t]]
// ---------------------------------------------------------------------------
__global__ void build_G(const int* __restrict__ lx, const float* __restrict__ TM) {
    int s = blockIdx.x;
    int t = threadIdx.x;
    int row = __ldg(lx + s);
    int col = __ldg(lx + t);
    g_G[s * LXN + t] = __ldg(TM + row * NTASKS + col);
}

// ---------------------------------------------------------------------------
// Phase 1 (standalone): blocked-scan chain, one 8-warp block per algo.
// Chain warp: branch-free 50-cyc/step serial path (tanh -> shfl -> fma, with
// g*eff / g*boost precomputed off-path). Bulk warps maintain the full 512-col
// state one chunk behind and feed boundary values. u published to g_u ONCE at
// the end (no flags / no cross-kernel sync).
// ---------------------------------------------------------------------------
__global__ void __launch_bounds__(256, 1) phase1(
    const int* __restrict__ lx, const float* __restrict__ diff,
    const float* __restrict__ eff_, const float* __restrict__ mem_,
    const float* __restrict__ boost_) {

    __shared__ float u_sh[LXN];
    __shared__ float c2_sh[LXN];
    __shared__ float Bnext[2][32];

    int a   = blockIdx.x;
    int tid = threadIdx.x;
    int w = tid >> 5, l = tid & 31;

    float mem = __ldg(mem_ + a), eff = __ldg(eff_ + a), boost = __ldg(boost_ + a);
    float m2 = mem * mem, m4 = m2 * m2, m8 = m4 * m4, m16 = m8 * m8;
    float M32 = m16 * m16;

    for (int t = tid; t < LXN; t += 256)
        c2_sh[t] = 0.5f / __ldg(diff + __ldg(lx + t));
    __syncthreads();

    if (w == 0) {
        // ---- chain warp ----
        float racc = 0.0f, racc2 = 0.0f;
        float c2l = c2_sh[l];
        float my_u = 0.0f;

#pragma unroll 1
        for (int c = 0; c < 16; ++c) {
            int t0 = c * 32;
            const float* gArow = g_G + t0 + l;
            const float* gBrow = g_G + t0 + 32 + l;
            bool hasB = (c < 15);

            float gAe[8], gAb[8], gBe[8], gBb[8];
#pragma unroll
            for (int q = 0; q < 8; ++q) {
                float ga = __ldg(gArow + (t0 + q) * LXN);
                float gb = hasB ? __ldg(gBrow + (t0 + q) * LXN) : 0.0f;
                gAe[q] = ga * eff;  gAb[q] = ga * boost;
                gBe[q] = gb * eff;  gBb[q] = gb * boost;
            }
#pragma unroll
            for (int k = 0; k < 32; ++k) {
                int q = k & 7;
                float th = tanh_fast(racc * c2l);          // all lanes compute
                float thb = __shfl_sync(FULLMASK, th, k);  // owner's value
                my_u = (l == k) ? fmaf(th, boost, eff) : my_u;
                racc  = fmaf(thb, gAb[q], fmaf(racc,  mem, gAe[q]));
                racc2 = fmaf(thb, gBb[q], fmaf(racc2, mem, gBe[q]));
                if (k + 8 < 32) {
                    float ga = __ldg(gArow + (t0 + k + 8) * LXN);
                    float gb = hasB ? __ldg(gBrow + (t0 + k + 8) * LXN) : 0.0f;
                    gAe[q] = ga * eff;  gAb[q] = ga * boost;
                    gBe[q] = gb * eff;  gBb[q] = gb * boost;
                }
            }
            u_sh[t0 + l] = my_u;
            __syncthreads();
            if (c < 15) {
                racc  = fmaf(Bnext[(c + 1) & 1][l], M32, racc2);
                racc2 = 0.0f;
                c2l   = c2_sh[t0 + 32 + l];
            }
        }
    } else {
        // ---- bulk warps 1..7 (one chunk behind) ----
        int base0 = (w - 1) * 32 + l;
        bool has3 = (base0 + 448 < LXN);
        float R0 = 0.0f, R1 = 0.0f, R2v = 0.0f;

#pragma unroll 1
        for (int c = 0; c < 16; ++c) {
            if (c >= 1) {
                int s0 = (c - 1) * 32;
                const float* g0 = g_G + base0;
#pragma unroll 8
                for (int k = 0; k < 32; ++k) {
                    float u = u_sh[s0 + k];
                    const float* gr = g0 + (s0 + k) * LXN;
                    R0 = fmaf(R0, mem, __ldg(gr) * u);
                    R1 = fmaf(R1, mem, __ldg(gr + 224) * u);
                    if (has3) R2v = fmaf(R2v, mem, __ldg(gr + 448) * u);
                }
            }
            int b = c + 1;
            if (b <= 15 && (w - 1) == (b % 7)) {
                int i = b / 7;
                float Rv = (i == 0) ? R0 : (i == 1) ? R1 : R2v;
                Bnext[b & 1][l] = Rv;
            }
            __syncthreads();
        }
    }

    // final publish, all 8 warps, coalesced
    __syncthreads();
    for (int t = tid; t < LXN; t += 256)
        g_u[a * LXN + t] = u_sh[t];
}

// ---------------------------------------------------------------------------
// Phase 2 (standalone): 65536 independent column scans, pure throughput.
// Per chunk: 32-LDG register prefetch (MLP=32), fma+tanh from registers
// (u broadcast from smem), STS.128 into padded transpose tile, 32 coalesced
// streaming STG rows.
// ---------------------------------------------------------------------------
__global__ void __launch_bounds__(256) phase2(
    const int* __restrict__ lx, const float* __restrict__ TM,
    const float* __restrict__ diff, const float* __restrict__ mem_,
    float* __restrict__ out) {

    __shared__ float u_sh[LXN];
    __shared__ int   off_sh[LXN];
    __shared__ float tbuf_all[8 * 32 * 36];

    int a   = blockIdx.y;
    int jb  = blockIdx.x;
    int tid = threadIdx.x;
    int w = tid >> 5, l = tid & 31;
    int j = jb * 256 + tid;
    float* tbuf = tbuf_all + w * (32 * 36);

    for (int i = tid; i < LXN; i += 256) {
        u_sh[i]   = g_u[a * LXN + i];
        off_sh[i] = __ldg(lx + i) << 10;
    }
    __syncthreads();

    float mem = __ldg(mem_ + a);
    float c2  = 0.5f / __ldg(diff + j);
    float r   = 0.0f;

    unsigned obase = (unsigned)(a * NTASKS + j) * 513u;
    stcs_f32(out + obase, 0.0f);                       // step-0 zeros
    unsigned tbase = (unsigned)(a * NTASKS + jb * 256 + w * 32) * 513u
                     + 1u + (unsigned)l;
    const float* TMj = TM + j;

#pragma unroll 1
    for (int c = 0; c < 16; ++c) {
        // 1) 32 independent LDGs (ptxas batches them: one ~L2-RT stall/chunk,
        //    hidden by co-resident warps)
        float v[32];
#pragma unroll
        for (int k = 0; k < 32; ++k)
            v[k] = __ldg(TMj + off_sh[c * 32 + k]);
        // 2) compute; pack 4 sigmoids -> STS.128
#pragma unroll
        for (int g = 0; g < 8; ++g) {
            float4 s4;
            r = fmaf(r, mem, v[4 * g + 0] * u_sh[c * 32 + 4 * g + 0]);
            s4.x = tanh_fast(r * c2);
            r = fmaf(r, mem, v[4 * g + 1] * u_sh[c * 32 + 4 * g + 1]);
            s4.y = tanh_fast(r * c2);
            r = fmaf(r, mem, v[4 * g + 2] * u_sh[c * 32 + 4 * g + 2]);
            s4.z = tanh_fast(r * c2);
            r = fmaf(r, mem, v[4 * g + 3] * u_sh[c * 32 + 4 * g + 3]);
            s4.w = tanh_fast(r * c2);
            *(float4*)(tbuf + l * 36 + g * 4) = s4;
        }
        __syncwarp();
        // 3) coalesced streaming stores (STG.32: odd 513 stride, not 16B-alignable)
        unsigned ob = tbase + (unsigned)(c * 32);
#pragma unroll 8
        for (int row = 0; row < 32; ++row)
            stcs_f32(out + ob + (unsigned)row * 513u, tbuf[row * 36 + l]);
        __syncwarp();
    }
}

// ---------------------------------------------------------------------------
extern "C" void kernel_launch(void* const* d_in, const int* in_sizes, int n_in,
                              void* d_out, int out_size) {
    const int*   lx    = (const int*)  d_in[0];
    const float* TM    = (const float*)d_in[1];
    const float* diff  = (const float*)d_in[2];
    const float* eff   = (const float*)d_in[3];
    const float* mem   = (const float*)d_in[4];
    const float* boost = (const float*)d_in[5];
    float* out = (float*)d_out;

    build_G<<<LXN, LXN>>>(lx, TM);
    phase1<<<NALGOS, 256>>>(lx, diff, eff, mem, boost);
    phase2<<<dim3(4, NALGOS), 256>>>(lx, TM, diff, mem, out);
}